// round 4
// baseline (speedup 1.0000x reference)
#include <cuda_runtime.h>
#include <cstdint>

#define Bn  256
#define Vn  2048
#define PDn 1024
#define MDn 512
#define Hn  512
#define W1LD (PDn + MDn)

#define KSPLIT 4             // hp split-K factor
#define KSEG  (PDn / KSPLIT) // 256
#define KC    16             // GEMM k-chunk

// Scratch (device globals; transposed layouts for the score kernel).
__device__ float g_hp_partT[KSPLIT * Hn * Bn]; // [s][h][b]
__device__ float g_hmT[Hn * Vn];               // [h][v]

__device__ __forceinline__ float fast_tanh(float x) {
    float y;
    asm("tanh.approx.f32 %0, %1;" : "=f"(y) : "f"(x));
    return y;
}

// Packed fp32x2 FMA (sm_100+/sm_103a; identical rounding to scalar FFMA).
__device__ __forceinline__ unsigned long long fma2(
    unsigned long long a, unsigned long long b, unsigned long long c) {
    unsigned long long d;
    asm("fma.rn.f32x2 %0, %1, %2, %3;" : "=l"(d) : "l"(a), "l"(b), "l"(c));
    return d;
}

// ---------------------------------------------------------------------------
// Unified GEMM, FFMA2 (f32x2) datapath. 384 blocks x 64 threads:
//   bid <  256 : hm tile 64v x 64h, K=512 -> g_hmT
//   bid >= 256 : hp tile 64b x 64h, K=256 split-K s -> g_hp_partT[s]
// Microtile 8m x 8n per thread via packed pairs:
//   A smem [k][m] pad 72          -> ulonglong2 LDS.128 gives natural m-pairs
//   W smem [k][2n] duplicated     -> ulonglong2 LDS.128 gives (w,w) dup pairs
// 32 fma2 / 6 LDS.128 per thread-kk => FMA-pipe-bound at 2x fp32 FLOP rate.
// Transposed coalesced epilogue via smem transpose (reuses operand smem).
// ---------------------------------------------------------------------------
#define AP 72    // As row pad (floats): 288B, 16B-aligned rows
#define WP 136   // Wd row pad (floats): 544B, 16B-aligned rows
#define TP 68    // transpose buffer pad: 272B, 16B-aligned rows

__global__ void __launch_bounds__(64) gemm_fused_kernel(
    const float* __restrict__ patient,
    const float* __restrict__ atc4,
    const float* __restrict__ W1)
{
    __shared__ union {
        struct { float As[KC * AP]; float Wd[KC * WP]; } s; // 13.3 KB
        float tb[64 * TP];                                  // 17.4 KB
    } sm;

    const int bid = blockIdx.x;
    const int tid = threadIdx.x;

    const float* A;
    float* C;
    int LDA, m0, n0, kA0, kW0, NCHUNK, ldc;

    if (bid < 256) {                 // hm
        A = atc4;  C = g_hmT;  LDA = MDn;  ldc = Vn;
        m0 = (bid & 31) * 64;        // v
        n0 = (bid >> 5) * 64;        // h
        kA0 = 0;  kW0 = PDn;
        NCHUNK = MDn / KC;           // 32
    } else {                         // hp split-K
        int t = bid - 256;
        int s = t & 3;
        A = patient;  LDA = PDn;  ldc = Bn;
        C = g_hp_partT + s * (Hn * Bn);
        m0 = ((t >> 2) & 3) * 64;    // b
        n0 = (t >> 4) * 64;          // h
        kA0 = s * KSEG;  kW0 = s * KSEG;
        NCHUNK = KSEG / KC;          // 16
    }

    // Compute map: 8x8 thread grid, 8m x 8n microtile.
    const int tmg = (tid & 7) * 8;
    const int tng = (tid >> 3) * 8;

    // Staging map: kk4 = float4 index in k (0..3), mm = base row (0..15).
    const int kk4 = tid & 3;
    const int mm  = tid >> 2;

    unsigned long long acc2[4][8];   // [m-pair][n]; bits(0.f,0.f)==0
    #pragma unroll
    for (int p = 0; p < 4; p++)
        #pragma unroll
        for (int j = 0; j < 8; j++) acc2[p][j] = 0ull;

    float4 rA[4], rW[4];

    auto ldg_chunk = [&](int k0) {
        #pragma unroll
        for (int r = 0; r < 4; r++) {
            rA[r] = *(const float4*)(A  + (size_t)(m0 + mm + 16 * r) * LDA
                                        + kA0 + k0 + kk4 * 4);
            rW[r] = *(const float4*)(W1 + (size_t)(n0 + mm + 16 * r) * W1LD
                                        + kW0 + k0 + kk4 * 4);
        }
    };
    auto sts_chunk = [&]() {
        const int kb = kk4 * 4;
        #pragma unroll
        for (int r = 0; r < 4; r++) {
            int row = mm + 16 * r;
            float a[4] = {rA[r].x, rA[r].y, rA[r].z, rA[r].w};
            float w[4] = {rW[r].x, rW[r].y, rW[r].z, rW[r].w};
            #pragma unroll
            for (int c = 0; c < 4; c++) {
                sm.s.As[(kb + c) * AP + row] = a[c];
                *(float2*)&sm.s.Wd[(kb + c) * WP + 2 * row] =
                    make_float2(w[c], w[c]);
            }
        }
    };

    ldg_chunk(0);
    sts_chunk();
    if (NCHUNK > 1) ldg_chunk(KC);
    __syncthreads();

    for (int c = 0; c < NCHUNK; c++) {
        #pragma unroll
        for (int kk = 0; kk < KC; kk++) {
            // m-pairs (natural) and duplicated w-pairs, zero pack instructions
            ulonglong2 a01_23 = *(const ulonglong2*)&sm.s.As[kk * AP + tmg];
            ulonglong2 a45_67 = *(const ulonglong2*)&sm.s.As[kk * AP + tmg + 4];
            ulonglong2 w01 = *(const ulonglong2*)&sm.s.Wd[kk * WP + 2 * tng];
            ulonglong2 w23 = *(const ulonglong2*)&sm.s.Wd[kk * WP + 2 * tng + 4];
            ulonglong2 w45 = *(const ulonglong2*)&sm.s.Wd[kk * WP + 2 * tng + 8];
            ulonglong2 w67 = *(const ulonglong2*)&sm.s.Wd[kk * WP + 2 * tng + 12];
            unsigned long long ap[4] = {a01_23.x, a01_23.y, a45_67.x, a45_67.y};
            unsigned long long wd[8] = {w01.x, w01.y, w23.x, w23.y,
                                        w45.x, w45.y, w67.x, w67.y};
            #pragma unroll
            for (int j = 0; j < 8; j++)
                #pragma unroll
                for (int p = 0; p < 4; p++)
                    acc2[p][j] = fma2(ap[p], wd[j], acc2[p][j]);
        }
        __syncthreads();
        if (c + 1 < NCHUNK) {
            sts_chunk();                       // chunk c+1 (regs from earlier)
            if (c + 2 < NCHUNK) ldg_chunk((c + 2) * KC);
            __syncthreads();
        }
    }

    // Epilogue: transpose through smem, then coalesced float4 row stores.
    #pragma unroll
    for (int j = 0; j < 8; j++)
        #pragma unroll
        for (int p = 0; p < 4; p++) {
            unsigned long long v = acc2[p][j];
            float lo = __uint_as_float((unsigned)(v & 0xffffffffu));
            float hi = __uint_as_float((unsigned)(v >> 32));
            sm.tb[(tng + j) * TP + tmg + 2 * p]     = lo;
            sm.tb[(tng + j) * TP + tmg + 2 * p + 1] = hi;
        }
    __syncthreads();
    {
        const int col4 = tid & 15;      // 16 float4 per 64-float row
        const int rsub = tid >> 4;      // 4 rows per pass
        #pragma unroll
        for (int pass = 0; pass < 16; pass++) {
            int row = pass * 4 + rsub;  // local h
            float4 v = *(const float4*)&sm.tb[row * TP + col4 * 4];
            *(float4*)&C[(size_t)(n0 + row) * ldc + m0 + col4 * 4] = v;
        }
    }
}

// ---------------------------------------------------------------------------
// Score: out[b,v] = b2 + sum_h w2[h] * tanh(hp[b,h] + b1[h] + hm[v,h])
// Tile 8b x 64v, 128 threads, micro 1b x 4v. grid = 1024 blocks (6.9 waves,
// ~1% tail vs 15.6% at 512). MUFU(tanh)-bound inner loop.
// ---------------------------------------------------------------------------
#define HC 64
__global__ void __launch_bounds__(128) score_kernel(
    const float* __restrict__ b1, const float* __restrict__ w2,
    const float* __restrict__ b2p, float* __restrict__ out)
{
    __shared__ float hp_sh[HC * 9];
    __shared__ float hm_sh[HC * 68];
    __shared__ float w2_sh[Hn];

    const int tid = threadIdx.x;
    const int v0  = blockIdx.x * 64;
    const int b0  = blockIdx.y * 8;
    const int tv  = (tid & 15) * 4;   // 4 v's
    const int tb  = tid >> 4;         // 1 b (0..7)

    ((float4*)w2_sh)[tid] = ((const float4*)w2)[tid];   // 128 x float4 = 512

    const int hpa_hh = tid >> 1;          // 0..63
    const int hpa_b4 = (tid & 1) * 4;     // 0,4

    float acc[4] = {};

    for (int h0 = 0; h0 < Hn; h0 += HC) {
        __syncthreads();
        // hp chunk [64h x 8b]: 4 split-K partials + b1, fixed order.
        {
            const float* p = g_hp_partT + (size_t)(h0 + hpa_hh) * Bn + b0 + hpa_b4;
            float4 s0 = *(const float4*)(p);
            float4 s1 = *(const float4*)(p + 1 * Hn * Bn);
            float4 s2 = *(const float4*)(p + 2 * Hn * Bn);
            float4 s3 = *(const float4*)(p + 3 * Hn * Bn);
            float bv = b1[h0 + hpa_hh];
            float* d = &hp_sh[hpa_hh * 9 + hpa_b4];
            d[0] = bv + s0.x + s1.x + s2.x + s3.x;
            d[1] = bv + s0.y + s1.y + s2.y + s3.y;
            d[2] = bv + s0.z + s1.z + s2.z + s3.z;
            d[3] = bv + s0.w + s1.w + s2.w + s3.w;
        }
        // hm chunk [64h x 64v]
        #pragma unroll
        for (int r = 0; r < 8; r++) {
            int idx = tid + r * 128;
            int hh  = idx >> 4;
            int v4  = (idx & 15) * 4;
            float4 m = *(const float4*)&g_hmT[(size_t)(h0 + hh) * Vn + v0 + v4];
            *(float4*)&hm_sh[hh * 68 + v4] = m;
        }
        __syncthreads();

        #pragma unroll 16
        for (int hh = 0; hh < HC; hh++) {
            float  wv  = w2_sh[h0 + hh];
            float  hpv = hp_sh[hh * 9 + tb];
            float4 m4  = *(const float4*)&hm_sh[hh * 68 + tv];
            acc[0] += wv * fast_tanh(hpv + m4.x);
            acc[1] += wv * fast_tanh(hpv + m4.y);
            acc[2] += wv * fast_tanh(hpv + m4.z);
            acc[3] += wv * fast_tanh(hpv + m4.w);
        }
    }

    const float b2 = *b2p;
    float4 o;
    o.x = acc[0] + b2; o.y = acc[1] + b2; o.z = acc[2] + b2; o.w = acc[3] + b2;
    *(float4*)&out[(size_t)(b0 + tb) * Vn + v0 + tv] = o;
}

extern "C" void kernel_launch(void* const* d_in, const int* in_sizes, int n_in,
                              void* d_out, int out_size) {
    const float* patient = (const float*)d_in[0];  // [B, PD]
    const float* atc4    = (const float*)d_in[1];  // [V, MD]
    const float* W1      = (const float*)d_in[2];  // [H, PD+MD]
    const float* b1      = (const float*)d_in[3];  // [H]
    const float* w2      = (const float*)d_in[4];  // [H]
    const float* b2      = (const float*)d_in[5];  // scalar
    float* out = (float*)d_out;                    // [B, V]

    gemm_fused_kernel<<<384, 64>>>(patient, atc4, W1);

    dim3 grid(Vn / 64, Bn / 8);    // 32 x 32 = 1024 blocks
    score_kernel<<<grid, 128>>>(b1, w2, b2, out);
}

// round 5
// speedup vs baseline: 1.1376x; 1.1376x over previous
#include <cuda_runtime.h>
#include <cuda_fp16.h>
#include <cstdint>

#define Bn  256
#define Vn  2048
#define PDn 1024
#define MDn 512
#define Hn  512
#define W1LD (PDn + MDn)

#define KSPLIT 4             // hp split-K factor
#define KSEG  (PDn / KSPLIT) // 256

// Scratch (device globals; transposed layouts for the score kernel).
__device__ float  g_hp_partT[KSPLIT * Hn * Bn]; // [s][h][b] fp32 partials
__device__ __half g_hmT[Hn * Vn];               // [h][v] fp16

__device__ __forceinline__ unsigned tanh2_f16(unsigned x) {
    unsigned y;
    asm("tanh.approx.f16x2 %0, %1;" : "=r"(y) : "r"(x));
    return y;
}

// ---------------------------------------------------------------------------
// Unified GEMM (round-2 proven structure). 384 blocks x 256 threads:
//   bid <  256 : hm tile 64v x 64h, K=512 -> g_hmT (fp16, transposed)
//   bid >= 256 : hp tile 64b x 64h, K=256 split-K s -> g_hp_partT[s] (fp32, T)
// 4x4 microtile, pad-68 LDS.128, register prefetch, single smem buffer.
// Epilogue: smem transpose (union reuse) -> coalesced row stores.
// ---------------------------------------------------------------------------
__global__ void __launch_bounds__(256) gemm_fused_kernel(
    const float* __restrict__ patient,
    const float* __restrict__ atc4,
    const float* __restrict__ W1)
{
    __shared__ union {
        struct { float As[32 * 68]; float Ws[32 * 68]; } s;  // 17408 B
        float tb[64 * 68];                                   // 17408 B
    } sm;

    const int bid = blockIdx.x;
    const int tid = threadIdx.x;

    const float* A;
    int LDA, m0, n0, kA0, kW0, KLEN, hp_slice = -1;

    if (bid < 256) {                 // hm
        A  = atc4;  LDA = MDn;
        m0 = (bid & 31) * 64;        // v
        n0 = (bid >> 5) * 64;        // h
        kA0 = 0;  kW0 = PDn;
        KLEN = MDn;                  // 512
    } else {                         // hp split-K
        int t = bid - 256;           // 0..127
        hp_slice = t & 3;
        A  = patient;  LDA = PDn;
        m0 = ((t >> 2) & 3) * 64;    // b
        n0 = (t >> 4) * 64;          // h
        kA0 = hp_slice * KSEG;  kW0 = hp_slice * KSEG;
        KLEN = KSEG;                 // 256
    }

    // Warp map: 32m x 16n per warp, LDS.128 reads.
    const int warp = tid >> 5, lane = tid & 31;
    const int wm = warp & 1, wn = warp >> 1;
    const int tm = (lane & 7) * 4 + wm * 32;
    const int tn = ((lane >> 3) & 3) * 4 + wn * 16;

    // Global-load map: 2 float4 per operand per thread per 32-k chunk.
    const int kk4 = tid & 7;
    const int mm  = tid >> 3;

    float acc[4][4] = {};
    float4 rA0, rA1, rW0, rW1;

    // Prefetch chunk 0
    {
        const float* ap = A + (size_t)(m0 + mm) * LDA + kA0 + kk4 * 4;
        rA0 = *(const float4*)ap;
        rA1 = *(const float4*)(ap + 32 * LDA);
        const float* wp = W1 + (size_t)(n0 + mm) * W1LD + kW0 + kk4 * 4;
        rW0 = *(const float4*)wp;
        rW1 = *(const float4*)(wp + 32 * W1LD);
    }

    for (int k0 = 0; k0 < KLEN; k0 += 32) {
        // Store prefetched chunk to shared (transposed [k][mn]).
        {
            int kb = kk4 * 4;
            float* as = sm.s.As;
            float* ws = sm.s.Ws;
            as[(kb + 0) * 68 + mm] = rA0.x;  as[(kb + 1) * 68 + mm] = rA0.y;
            as[(kb + 2) * 68 + mm] = rA0.z;  as[(kb + 3) * 68 + mm] = rA0.w;
            as[(kb + 0) * 68 + mm + 32] = rA1.x;  as[(kb + 1) * 68 + mm + 32] = rA1.y;
            as[(kb + 2) * 68 + mm + 32] = rA1.z;  as[(kb + 3) * 68 + mm + 32] = rA1.w;
            ws[(kb + 0) * 68 + mm] = rW0.x;  ws[(kb + 1) * 68 + mm] = rW0.y;
            ws[(kb + 2) * 68 + mm] = rW0.z;  ws[(kb + 3) * 68 + mm] = rW0.w;
            ws[(kb + 0) * 68 + mm + 32] = rW1.x;  ws[(kb + 1) * 68 + mm + 32] = rW1.y;
            ws[(kb + 2) * 68 + mm + 32] = rW1.z;  ws[(kb + 3) * 68 + mm + 32] = rW1.w;
        }
        __syncthreads();

        // Prefetch next chunk while computing this one.
        if (k0 + 32 < KLEN) {
            const float* ap = A + (size_t)(m0 + mm) * LDA + kA0 + k0 + 32 + kk4 * 4;
            rA0 = *(const float4*)ap;
            rA1 = *(const float4*)(ap + 32 * LDA);
            const float* wp = W1 + (size_t)(n0 + mm) * W1LD + kW0 + k0 + 32 + kk4 * 4;
            rW0 = *(const float4*)wp;
            rW1 = *(const float4*)(wp + 32 * W1LD);
        }

        #pragma unroll
        for (int kk = 0; kk < 32; kk++) {
            float4 a4 = *(const float4*)&sm.s.As[kk * 68 + tm];
            float4 w4 = *(const float4*)&sm.s.Ws[kk * 68 + tn];
            float a[4] = {a4.x, a4.y, a4.z, a4.w};
            float w[4] = {w4.x, w4.y, w4.z, w4.w};
            #pragma unroll
            for (int i = 0; i < 4; i++)
                #pragma unroll
                for (int j = 0; j < 4; j++)
                    acc[i][j] += a[i] * w[j];
        }
        __syncthreads();
    }

    // Transpose through smem (safe: last compute consumed As/Ws before sync).
    #pragma unroll
    for (int j = 0; j < 4; j++)
        #pragma unroll
        for (int i = 0; i < 4; i++)
            sm.tb[(tn + j) * 68 + tm + i] = acc[i][j];
    __syncthreads();

    // Coalesced transposed stores: 64 rows of h, 64 cols of m(v|b).
    const int row = tid >> 2;        // local h, 0..63
    const int seg = tid & 3;         // 16-col segment

    float f[16];
    #pragma unroll
    for (int c = 0; c < 4; c++) {
        float4 v = *(const float4*)&sm.tb[row * 68 + seg * 16 + c * 4];
        f[c * 4 + 0] = v.x; f[c * 4 + 1] = v.y;
        f[c * 4 + 2] = v.z; f[c * 4 + 3] = v.w;
    }

    if (hp_slice < 0) {
        // hm: convert to fp16, 16 halves = 2 uint4 stores.
        __half h[16];
        #pragma unroll
        for (int c = 0; c < 16; c++) h[c] = __float2half_rn(f[c]);
        __half* dst = g_hmT + (size_t)(n0 + row) * Vn + m0 + seg * 16;
        *(uint4*)(dst)     = *(uint4*)&h[0];
        *(uint4*)(dst + 8) = *(uint4*)&h[8];
    } else {
        float* dst = g_hp_partT + (size_t)hp_slice * (Hn * Bn)
                   + (size_t)(n0 + row) * Bn + m0 + seg * 16;
        #pragma unroll
        for (int c = 0; c < 4; c++)
            *(float4*)(dst + c * 4) = make_float4(f[c*4], f[c*4+1], f[c*4+2], f[c*4+3]);
    }
}

// ---------------------------------------------------------------------------
// Score: out[b,v] = b2 + sum_h w2[h] * tanh(hp[b,h] + b1[h] + hm[v,h])
// fp16x2 tanh path: 2 tanhs per MUFU op (halved MUFU floor). hp,hm quantized
// to fp16; x via HADD2; accumulate in fp32 (F2F + FFMA) -> no drift.
// Tile 8b x 64v, 128 threads, micro 1b x 4v, grid 1024.
// ---------------------------------------------------------------------------
#define HC 64
__global__ void __launch_bounds__(128) score_kernel(
    const float* __restrict__ b1, const float* __restrict__ w2,
    const float* __restrict__ b2p, float* __restrict__ out)
{
    __shared__ __half2 hp_sh[HC * 9];    // [hh][b] duplicated pairs
    __shared__ __half2 hm_sh[HC * 36];   // [hh][v2] (pad 36 -> 144B rows, 16B-aligned)
    __shared__ float   w2_sh[Hn];

    const int tid = threadIdx.x;
    const int v0  = blockIdx.x * 64;
    const int b0  = blockIdx.y * 8;
    const int tvh = (tid & 15) * 2;   // half2 index of first v-pair
    const int tb  = tid >> 4;         // 0..7

    ((float4*)w2_sh)[tid] = ((const float4*)w2)[tid];   // 128 x float4 = 512

    const int hpa_hh = tid >> 1;          // 0..63
    const int hpa_b4 = (tid & 1) * 4;     // 0,4

    float acc[4] = {};

    for (int h0 = 0; h0 < Hn; h0 += HC) {
        __syncthreads();
        // hp chunk [64h x 8b]: 4 split-K fp32 partials + b1 (fixed order),
        // then quantize to duplicated half2.
        {
            const float* p = g_hp_partT + (size_t)(h0 + hpa_hh) * Bn + b0 + hpa_b4;
            float4 s0 = *(const float4*)(p);
            float4 s1 = *(const float4*)(p + 1 * Hn * Bn);
            float4 s2 = *(const float4*)(p + 2 * Hn * Bn);
            float4 s3 = *(const float4*)(p + 3 * Hn * Bn);
            float bv = b1[h0 + hpa_hh];
            float v0f = bv + s0.x + s1.x + s2.x + s3.x;
            float v1f = bv + s0.y + s1.y + s2.y + s3.y;
            float v2f = bv + s0.z + s1.z + s2.z + s3.z;
            float v3f = bv + s0.w + s1.w + s2.w + s3.w;
            __half2* d = &hp_sh[hpa_hh * 9 + hpa_b4];
            d[0] = __half2half2(__float2half_rn(v0f));
            d[1] = __half2half2(__float2half_rn(v1f));
            d[2] = __half2half2(__float2half_rn(v2f));
            d[3] = __half2half2(__float2half_rn(v3f));
        }
        // hm chunk [64h x 64v] fp16: 4096 halves = 512 uint4; 4 per thread.
        #pragma unroll
        for (int r = 0; r < 4; r++) {
            int idx = tid + r * 128;
            int hh  = idx >> 3;
            int s   = idx & 7;
            uint4 m = *(const uint4*)(g_hmT + (size_t)(h0 + hh) * Vn + v0 + s * 8);
            *(uint4*)&hm_sh[hh * 36 + s * 4] = m;
        }
        __syncthreads();

        #pragma unroll 16
        for (int hh = 0; hh < HC; hh++) {
            float   wv  = w2_sh[h0 + hh];
            __half2 hp2 = hp_sh[hh * 9 + tb];
            uint2   m2  = *(const uint2*)&hm_sh[hh * 36 + tvh];
            __half2 x0  = __hadd2(*(__half2*)&m2.x, hp2);
            __half2 x1  = __hadd2(*(__half2*)&m2.y, hp2);
            unsigned t0 = tanh2_f16(*(unsigned*)&x0);
            unsigned t1 = tanh2_f16(*(unsigned*)&x1);
            float2 f0 = __half22float2(*(__half2*)&t0);
            float2 f1 = __half22float2(*(__half2*)&t1);
            acc[0] += wv * f0.x;
            acc[1] += wv * f0.y;
            acc[2] += wv * f1.x;
            acc[3] += wv * f1.y;
        }
    }

    const float b2 = *b2p;
    float4 o;
    o.x = acc[0] + b2; o.y = acc[1] + b2; o.z = acc[2] + b2; o.w = acc[3] + b2;
    *(float4*)&out[(size_t)(b0 + tb) * Vn + v0 + (tid & 15) * 4] = o;
}

extern "C" void kernel_launch(void* const* d_in, const int* in_sizes, int n_in,
                              void* d_out, int out_size) {
    const float* patient = (const float*)d_in[0];  // [B, PD]
    const float* atc4    = (const float*)d_in[1];  // [V, MD]
    const float* W1      = (const float*)d_in[2];  // [H, PD+MD]
    const float* b1      = (const float*)d_in[3];  // [H]
    const float* w2      = (const float*)d_in[4];  // [H]
    const float* b2      = (const float*)d_in[5];  // scalar
    float* out = (float*)d_out;                    // [B, V]

    gemm_fused_kernel<<<384, 256>>>(patient, atc4, W1);

    dim3 grid(Vn / 64, Bn / 8);    // 32 x 32 = 1024 blocks
    score_kernel<<<grid, 128>>>(b1, w2, b2, out);
}

// round 6
// speedup vs baseline: 1.1389x; 1.0011x over previous
#include <cuda_runtime.h>
#include <cuda_fp16.h>
#include <cstdint>

#define Bn  256
#define Vn  2048
#define PDn 1024
#define MDn 512
#define Hn  512
#define W1LD (PDn + MDn)

#define KSPLIT 4             // hp split-K factor
#define KSEG  (PDn / KSPLIT) // 256

// Scratch: natural layouts for the MMA score kernel.
__device__ float  g_hp_part[KSPLIT * Bn * Hn]; // [s][b][h] fp32 partials
__device__ __half g_hm[Vn * Hn];               // [v][h] fp16

__device__ __forceinline__ unsigned tanh2_f16(unsigned x) {
    unsigned y;
    asm("tanh.approx.f16x2 %0, %1;" : "=r"(y) : "r"(x));
    return y;
}
__device__ __forceinline__ unsigned hadd2u(unsigned a, unsigned b) {
    unsigned d;
    asm("add.rn.f16x2 %0, %1, %2;" : "=r"(d) : "r"(a), "r"(b));
    return d;
}
__device__ __forceinline__ void mma_16816(float c[4],
    unsigned a0, unsigned a1, unsigned a2, unsigned a3,
    unsigned b0, unsigned b1)
{
    asm volatile(
        "mma.sync.aligned.m16n8k16.row.col.f32.f16.f16.f32 "
        "{%0,%1,%2,%3}, {%4,%5,%6,%7}, {%8,%9}, {%0,%1,%2,%3};"
        : "+f"(c[0]), "+f"(c[1]), "+f"(c[2]), "+f"(c[3])
        : "r"(a0), "r"(a1), "r"(a2), "r"(a3), "r"(b0), "r"(b1));
}

// ---------------------------------------------------------------------------
// Unified GEMM — round-2 proven structure (direct coalesced row stores).
// 384 blocks x 256 threads:
//   bid <  256 : hm tile 64v x 64h, K=512 -> g_hm   (fp16, row-major [v][h])
//   bid >= 256 : hp tile 64b x 64h, K=256 split-K s -> g_hp_part[s] ([b][h])
// 4x4 microtile, pad-68 LDS.128 operand reads, register prefetch.
// ---------------------------------------------------------------------------
__global__ void __launch_bounds__(256) gemm_fused_kernel(
    const float* __restrict__ patient,
    const float* __restrict__ atc4,
    const float* __restrict__ W1)
{
    __shared__ float As[32 * 68];
    __shared__ float Ws[32 * 68];

    const int bid = blockIdx.x;
    const int tid = threadIdx.x;

    const float* A;
    int LDA, m0, n0, kA0, kW0, KLEN, hp_slice = -1;

    if (bid < 256) {                 // hm
        A  = atc4;  LDA = MDn;
        m0 = (bid & 31) * 64;        // v
        n0 = (bid >> 5) * 64;        // h
        kA0 = 0;  kW0 = PDn;
        KLEN = MDn;                  // 512
    } else {                         // hp split-K
        int t = bid - 256;           // 0..127
        hp_slice = t & 3;
        A  = patient;  LDA = PDn;
        m0 = ((t >> 2) & 3) * 64;    // b
        n0 = (t >> 4) * 64;          // h
        kA0 = hp_slice * KSEG;  kW0 = hp_slice * KSEG;
        KLEN = KSEG;                 // 256
    }

    const int warp = tid >> 5, lane = tid & 31;
    const int wm = warp & 1, wn = warp >> 1;
    const int tm = (lane & 7) * 4 + wm * 32;
    const int tn = ((lane >> 3) & 3) * 4 + wn * 16;

    const int kk4 = tid & 7;
    const int mm  = tid >> 3;

    float acc[4][4] = {};
    float4 rA0, rA1, rW0, rW1;

    {   // prefetch chunk 0
        const float* ap = A + (size_t)(m0 + mm) * LDA + kA0 + kk4 * 4;
        rA0 = *(const float4*)ap;
        rA1 = *(const float4*)(ap + 32 * LDA);
        const float* wp = W1 + (size_t)(n0 + mm) * W1LD + kW0 + kk4 * 4;
        rW0 = *(const float4*)wp;
        rW1 = *(const float4*)(wp + 32 * W1LD);
    }

    for (int k0 = 0; k0 < KLEN; k0 += 32) {
        {
            int kb = kk4 * 4;
            As[(kb + 0) * 68 + mm] = rA0.x;  As[(kb + 1) * 68 + mm] = rA0.y;
            As[(kb + 2) * 68 + mm] = rA0.z;  As[(kb + 3) * 68 + mm] = rA0.w;
            As[(kb + 0) * 68 + mm + 32] = rA1.x;  As[(kb + 1) * 68 + mm + 32] = rA1.y;
            As[(kb + 2) * 68 + mm + 32] = rA1.z;  As[(kb + 3) * 68 + mm + 32] = rA1.w;
            Ws[(kb + 0) * 68 + mm] = rW0.x;  Ws[(kb + 1) * 68 + mm] = rW0.y;
            Ws[(kb + 2) * 68 + mm] = rW0.z;  Ws[(kb + 3) * 68 + mm] = rW0.w;
            Ws[(kb + 0) * 68 + mm + 32] = rW1.x;  Ws[(kb + 1) * 68 + mm + 32] = rW1.y;
            Ws[(kb + 2) * 68 + mm + 32] = rW1.z;  Ws[(kb + 3) * 68 + mm + 32] = rW1.w;
        }
        __syncthreads();

        if (k0 + 32 < KLEN) {
            const float* ap = A + (size_t)(m0 + mm) * LDA + kA0 + k0 + 32 + kk4 * 4;
            rA0 = *(const float4*)ap;
            rA1 = *(const float4*)(ap + 32 * LDA);
            const float* wp = W1 + (size_t)(n0 + mm) * W1LD + kW0 + k0 + 32 + kk4 * 4;
            rW0 = *(const float4*)wp;
            rW1 = *(const float4*)(wp + 32 * W1LD);
        }

        #pragma unroll
        for (int kk = 0; kk < 32; kk++) {
            float4 a4 = *(const float4*)&As[kk * 68 + tm];
            float4 w4 = *(const float4*)&Ws[kk * 68 + tn];
            float a[4] = {a4.x, a4.y, a4.z, a4.w};
            float w[4] = {w4.x, w4.y, w4.z, w4.w};
            #pragma unroll
            for (int i = 0; i < 4; i++)
                #pragma unroll
                for (int j = 0; j < 4; j++)
                    acc[i][j] += a[i] * w[j];
        }
        __syncthreads();
    }

    if (hp_slice < 0) {
        // hm: fp16 row-major [v][h], uint2 (4-half) stores
        #pragma unroll
        for (int i = 0; i < 4; i++) {
            __half h4[4];
            h4[0] = __float2half_rn(acc[i][0]);
            h4[1] = __float2half_rn(acc[i][1]);
            h4[2] = __float2half_rn(acc[i][2]);
            h4[3] = __float2half_rn(acc[i][3]);
            *(uint2*)&g_hm[(size_t)(m0 + tm + i) * Hn + n0 + tn] = *(uint2*)h4;
        }
    } else {
        float* C = g_hp_part + (size_t)hp_slice * (Bn * Hn);
        #pragma unroll
        for (int i = 0; i < 4; i++)
            *(float4*)&C[(size_t)(m0 + tm + i) * Hn + n0 + tn] =
                make_float4(acc[i][0], acc[i][1], acc[i][2], acc[i][3]);
    }
}

// ---------------------------------------------------------------------------
// Score via HMMA: out[b,v] = b2 + sum_h w2[h]*tanh(hp[b,h]+b1[h]+hm[v,h]).
// mma.m16n8k16: A = tanh(hp+hm) [16v x 16h] fp16 (computed via HADD2 + f16x2
// tanh, laid out directly in fragment registers), B = w2 chunk replicated in
// all 8 n-cols (cols identical -> any C col is the score), C = fp32 accum.
// Block 128 thr (4 warps), tile 64v x 8b; warp = 16v x 8b. Grid 1024.
// hm smem rows stride 72 halves -> A-frag LDS.32 conflict-free.
// ---------------------------------------------------------------------------
__global__ void __launch_bounds__(128) score_kernel(
    const float* __restrict__ b1, const float* __restrict__ w2,
    const float* __restrict__ b2p, float* __restrict__ out)
{
    __shared__ __half hm_sh[64 * 72];   // [v][h] chunk
    __shared__ __half hp_sh[8 * 72];    // [b][h] chunk (partials summed + b1)
    __shared__ __half w2h_sh[Hn];       // w2 fp16

    const int tid  = threadIdx.x;
    const int v0   = blockIdx.x * 64;
    const int b0   = blockIdx.y * 8;
    const int lane = tid & 31;
    const int g    = lane >> 2;         // group 0..7
    const int t    = lane & 3;          // thread-in-group
    const int vbase = (tid >> 5) * 16;  // warp's v offset

    // w2 -> fp16 once (covered by first __syncthreads)
    {
        float4 w = ((const float4*)w2)[tid];
        __half h4[4] = { __float2half_rn(w.x), __float2half_rn(w.y),
                         __float2half_rn(w.z), __float2half_rn(w.w) };
        *(uint2*)&w2h_sh[tid * 4] = *(uint2*)h4;
    }

    float acc[8][4];
    #pragma unroll
    for (int b = 0; b < 8; b++)
        #pragma unroll
        for (int c = 0; c < 4; c++) acc[b][c] = 0.0f;

    for (int h0 = 0; h0 < Hn; h0 += 64) {
        __syncthreads();
        // stage hm [64v x 64h] fp16: 512 uint4, 4 per thread
        #pragma unroll
        for (int r = 0; r < 4; r++) {
            int idx = tid + r * 128;
            int vv  = idx >> 3, q = idx & 7;
            uint4 m = *(const uint4*)(g_hm + (size_t)(v0 + vv) * Hn + h0 + q * 8);
            *(uint4*)&hm_sh[vv * 72 + q * 8] = m;
        }
        // stage hp [8b x 64h]: sum 4 split-K partials + b1 (fixed order), ->fp16
        {
            int b = tid >> 4, q = tid & 15;
            const float* p = g_hp_part + (size_t)(b0 + b) * Hn + h0 + q * 4;
            float4 s0 = *(const float4*)(p);
            float4 s1 = *(const float4*)(p + 1 * Bn * Hn);
            float4 s2 = *(const float4*)(p + 2 * Bn * Hn);
            float4 s3 = *(const float4*)(p + 3 * Bn * Hn);
            float4 bb = *(const float4*)(b1 + h0 + q * 4);
            __half h4[4];
            h4[0] = __float2half_rn(bb.x + s0.x + s1.x + s2.x + s3.x);
            h4[1] = __float2half_rn(bb.y + s0.y + s1.y + s2.y + s3.y);
            h4[2] = __float2half_rn(bb.z + s0.z + s1.z + s2.z + s3.z);
            h4[3] = __float2half_rn(bb.w + s0.w + s1.w + s2.w + s3.w);
            *(uint2*)&hp_sh[b * 72 + q * 4] = *(uint2*)h4;
        }
        __syncthreads();

        const __half* hmr0 = &hm_sh[(vbase + g) * 72];
        const __half* hmr1 = &hm_sh[(vbase + g + 8) * 72];

        #pragma unroll
        for (int c = 0; c < 4; c++) {
            const int hb = c * 16;
            // hm fragment pairs (shared across all 8 b)
            unsigned m00 = *(const unsigned*)&hmr0[hb + 2 * t];
            unsigned m10 = *(const unsigned*)&hmr1[hb + 2 * t];
            unsigned m01 = *(const unsigned*)&hmr0[hb + 2 * t + 8];
            unsigned m11 = *(const unsigned*)&hmr1[hb + 2 * t + 8];
            // B fragment = w2 pairs (all 8 n-cols identical)
            unsigned bw0 = *(const unsigned*)&w2h_sh[h0 + hb + 2 * t];
            unsigned bw1 = *(const unsigned*)&w2h_sh[h0 + hb + 2 * t + 8];
            #pragma unroll
            for (int b = 0; b < 8; b++) {
                unsigned p0 = *(const unsigned*)&hp_sh[b * 72 + hb + 2 * t];
                unsigned p1 = *(const unsigned*)&hp_sh[b * 72 + hb + 2 * t + 8];
                unsigned a0 = tanh2_f16(hadd2u(m00, p0));
                unsigned a1 = tanh2_f16(hadd2u(m10, p0));
                unsigned a2 = tanh2_f16(hadd2u(m01, p1));
                unsigned a3 = tanh2_f16(hadd2u(m11, p1));
                mma_16816(acc[b], a0, a1, a2, a3, bw0, bw1);
            }
        }
    }

    // Epilogue: all C columns equal; lanes t==0 hold rows g (c0) and g+8 (c2).
    const float b2 = *b2p;
    if (t == 0) {
        #pragma unroll
        for (int b = 0; b < 8; b++) {
            out[(size_t)(b0 + b) * Vn + v0 + vbase + g]     = acc[b][0] + b2;
            out[(size_t)(b0 + b) * Vn + v0 + vbase + g + 8] = acc[b][2] + b2;
        }
    }
}

extern "C" void kernel_launch(void* const* d_in, const int* in_sizes, int n_in,
                              void* d_out, int out_size) {
    const float* patient = (const float*)d_in[0];  // [B, PD]
    const float* atc4    = (const float*)d_in[1];  // [V, MD]
    const float* W1      = (const float*)d_in[2];  // [H, PD+MD]
    const float* b1      = (const float*)d_in[3];  // [H]
    const float* w2      = (const float*)d_in[4];  // [H]
    const float* b2      = (const float*)d_in[5];  // scalar
    float* out = (float*)d_out;                    // [B, V]

    gemm_fused_kernel<<<384, 256>>>(patient, atc4, W1);

    dim3 grid(Vn / 64, Bn / 8);    // 32 x 32 = 1024 blocks
    score_kernel<<<grid, 128>>>(b1, w2, b2, out);
}

// round 7
// speedup vs baseline: 1.5487x; 1.3599x over previous
#include <cuda_runtime.h>
#include <cuda_fp16.h>
#include <cstdint>

#define Bn  256
#define Vn  2048
#define PDn 1024
#define MDn 512
#define Hn  512
#define W1LD (PDn + MDn)

// fp16 copies of inputs + intermediates (device globals; no allocations).
__device__ __half g_patH[Bn * PDn];
__device__ __half g_atcH[Vn * MDn];
__device__ __half g_W1H[Hn * W1LD];
__device__ __half g_hm[Vn * Hn];    // [v][h]
__device__ __half g_hpH[Bn * Hn];   // [b][h], b1 folded in

__device__ __forceinline__ unsigned tanh2_f16(unsigned x) {
    unsigned y;
    asm("tanh.approx.f16x2 %0, %1;" : "=r"(y) : "r"(x));
    return y;
}
__device__ __forceinline__ unsigned hadd2u(unsigned a, unsigned b) {
    unsigned d;
    asm("add.rn.f16x2 %0, %1, %2;" : "=r"(d) : "r"(a), "r"(b));
    return d;
}
__device__ __forceinline__ void mma_16816(float c[4],
    unsigned a0, unsigned a1, unsigned a2, unsigned a3,
    unsigned b0, unsigned b1)
{
    asm volatile(
        "mma.sync.aligned.m16n8k16.row.col.f32.f16.f16.f32 "
        "{%0,%1,%2,%3}, {%4,%5,%6,%7}, {%8,%9}, {%0,%1,%2,%3};"
        : "+f"(c[0]), "+f"(c[1]), "+f"(c[2]), "+f"(c[3])
        : "r"(a0), "r"(a1), "r"(a2), "r"(a3), "r"(b0), "r"(b1));
}

// ---------------------------------------------------------------------------
// Convert inputs fp32 -> fp16 (memory-bound, ~3us).
// ---------------------------------------------------------------------------
#define NP4 (Bn * PDn / 4)       // 65536
#define NA4 (Vn * MDn / 4)       // 262144
#define NW4 (Hn * W1LD / 4)      // 196608
__global__ void __launch_bounds__(256) convert_kernel(
    const float* __restrict__ patient,
    const float* __restrict__ atc4,
    const float* __restrict__ W1)
{
    int i = blockIdx.x * 256 + threadIdx.x;
    const float* src;
    __half* dst;
    int off;
    if (i < NP4)            { src = patient; dst = g_patH; off = i; }
    else if (i < NP4 + NA4) { src = atc4;    dst = g_atcH; off = i - NP4; }
    else                    { src = W1;      dst = g_W1H;  off = i - NP4 - NA4; }
    float4 v = ((const float4*)src)[off];
    __half h[4] = { __float2half_rn(v.x), __float2half_rn(v.y),
                    __float2half_rn(v.z), __float2half_rn(v.w) };
    *(uint2*)(dst + off * 4) = *(uint2*)h;
}

// ---------------------------------------------------------------------------
// HMMA GEMM. 144 blocks x 256 threads (8 warps), block tile 128m x 64h:
//   bid < 128 : hm tile (v), K=512  -> g_hm fp16
//   bid >= 128: hp tile (b), K=1024 -> g_hpH fp16 (+ b1 folded)
// Warp tile 32m x 32n = 2x4 mma(m16n8k16) tiles, fp32 accumulators.
// smem [row][72-half] pad -> all fragment LDS conflict-free ((4g+t)%32 unique).
// ---------------------------------------------------------------------------
__global__ void __launch_bounds__(256) hmma_gemm_kernel(const float* __restrict__ b1)
{
    __shared__ __half As[128 * 72];  // 18 KB
    __shared__ __half Ws[64 * 72];   // 9 KB

    const int bid = blockIdx.x;
    const int tid = threadIdx.x;

    const __half* A;
    int LDA, m0, n0, kW0, KLEN;
    bool is_hp;
    if (bid < 128) {
        A = g_atcH;  LDA = MDn;
        m0 = (bid & 15) * 128;  n0 = (bid >> 4) * 64;
        kW0 = PDn;  KLEN = MDn;  is_hp = false;
    } else {
        int t = bid - 128;      // 0..15
        A = g_patH;  LDA = PDn;
        m0 = (t & 1) * 128;  n0 = (t >> 1) * 64;
        kW0 = 0;  KLEN = PDn;  is_hp = true;
    }

    const int wid = tid >> 5, lane = tid & 31;
    const int g = lane >> 2, t4 = lane & 3;
    const int wm = wid & 3, wn = wid >> 2;

    float acc[2][4][4];
    #pragma unroll
    for (int i = 0; i < 2; i++)
        #pragma unroll
        for (int j = 0; j < 4; j++)
            #pragma unroll
            for (int c = 0; c < 4; c++) acc[i][j][c] = 0.0f;

    uint4 rA[4], rW[2];
    auto ldg = [&](int k0) {
        #pragma unroll
        for (int it = 0; it < 4; it++) {
            int idx = tid + it * 256, r = idx >> 3, q = idx & 7;
            rA[it] = *(const uint4*)(A + (size_t)(m0 + r) * LDA + k0 + q * 8);
        }
        #pragma unroll
        for (int it = 0; it < 2; it++) {
            int idx = tid + it * 256, r = idx >> 3, q = idx & 7;
            rW[it] = *(const uint4*)(g_W1H + (size_t)(n0 + r) * W1LD + kW0 + k0 + q * 8);
        }
    };
    auto sts = [&]() {
        #pragma unroll
        for (int it = 0; it < 4; it++) {
            int idx = tid + it * 256, r = idx >> 3, q = idx & 7;
            *(uint4*)&As[r * 72 + q * 8] = rA[it];
        }
        #pragma unroll
        for (int it = 0; it < 2; it++) {
            int idx = tid + it * 256, r = idx >> 3, q = idx & 7;
            *(uint4*)&Ws[r * 72 + q * 8] = rW[it];
        }
    };

    const int NCH = KLEN / 64;
    ldg(0);
    sts();
    if (NCH > 1) ldg(64);
    __syncthreads();

    for (int c = 0; c < NCH; c++) {
        #pragma unroll
        for (int ks = 0; ks < 4; ks++) {
            const int kb = ks * 16;
            unsigned a[2][4], b[4][2];
            #pragma unroll
            for (int i = 0; i < 2; i++) {
                int r0 = wm * 32 + i * 16 + g, r1 = r0 + 8;
                a[i][0] = *(const unsigned*)&As[r0 * 72 + kb + 2 * t4];
                a[i][1] = *(const unsigned*)&As[r1 * 72 + kb + 2 * t4];
                a[i][2] = *(const unsigned*)&As[r0 * 72 + kb + 2 * t4 + 8];
                a[i][3] = *(const unsigned*)&As[r1 * 72 + kb + 2 * t4 + 8];
            }
            #pragma unroll
            for (int j = 0; j < 4; j++) {
                int n = wn * 32 + j * 8 + g;
                b[j][0] = *(const unsigned*)&Ws[n * 72 + kb + 2 * t4];
                b[j][1] = *(const unsigned*)&Ws[n * 72 + kb + 2 * t4 + 8];
            }
            #pragma unroll
            for (int i = 0; i < 2; i++)
                #pragma unroll
                for (int j = 0; j < 4; j++)
                    mma_16816(acc[i][j], a[i][0], a[i][1], a[i][2], a[i][3],
                              b[j][0], b[j][1]);
        }
        __syncthreads();
        if (c + 1 < NCH) {
            sts();
            if (c + 2 < NCH) ldg((c + 2) * 64);
            __syncthreads();
        }
    }

    // Epilogue: C rows = m (v|b), cols = h.
    #pragma unroll
    for (int i = 0; i < 2; i++) {
        int vr0 = m0 + wm * 32 + i * 16 + g, vr1 = vr0 + 8;
        #pragma unroll
        for (int j = 0; j < 4; j++) {
            int cn = n0 + wn * 32 + j * 8 + 2 * t4;
            if (!is_hp) {
                *(__half2*)&g_hm[(size_t)vr0 * Hn + cn] =
                    __floats2half2_rn(acc[i][j][0], acc[i][j][1]);
                *(__half2*)&g_hm[(size_t)vr1 * Hn + cn] =
                    __floats2half2_rn(acc[i][j][2], acc[i][j][3]);
            } else {
                float2 bb = *(const float2*)&b1[cn];
                *(__half2*)&g_hpH[(size_t)vr0 * Hn + cn] =
                    __floats2half2_rn(acc[i][j][0] + bb.x, acc[i][j][1] + bb.y);
                *(__half2*)&g_hpH[(size_t)vr1 * Hn + cn] =
                    __floats2half2_rn(acc[i][j][2] + bb.x, acc[i][j][3] + bb.y);
            }
        }
    }
}

// ---------------------------------------------------------------------------
// Score via HMMA (round-6 structure): out[b,v] = b2 + sum_h w2[h]*tanh(...)
// hp staging now a direct fp16 copy (b1 pre-folded) -> far fewer regs/instrs.
// __launch_bounds__(128, 8): 8 blocks/SM -> 50% occ to hide LDS/MUFU latency.
// ---------------------------------------------------------------------------
__global__ void __launch_bounds__(128, 8) score_kernel(
    const float* __restrict__ w2, const float* __restrict__ b2p,
    float* __restrict__ out)
{
    __shared__ __half hm_sh[64 * 72];
    __shared__ __half hp_sh[8 * 72];
    __shared__ __half w2h_sh[Hn];

    const int tid  = threadIdx.x;
    const int v0   = blockIdx.x * 64;
    const int b0   = blockIdx.y * 8;
    const int lane = tid & 31;
    const int g    = lane >> 2;
    const int t    = lane & 3;
    const int vbase = (tid >> 5) * 16;

    {   // w2 -> fp16 once (covered by first __syncthreads)
        float4 w = ((const float4*)w2)[tid];
        __half h4[4] = { __float2half_rn(w.x), __float2half_rn(w.y),
                         __float2half_rn(w.z), __float2half_rn(w.w) };
        *(uint2*)&w2h_sh[tid * 4] = *(uint2*)h4;
    }

    float acc[8][4];
    #pragma unroll
    for (int b = 0; b < 8; b++)
        #pragma unroll
        for (int c = 0; c < 4; c++) acc[b][c] = 0.0f;

    for (int h0 = 0; h0 < Hn; h0 += 64) {
        __syncthreads();
        #pragma unroll
        for (int r = 0; r < 4; r++) {   // hm [64v x 64h]
            int idx = tid + r * 128;
            int vv = idx >> 3, q = idx & 7;
            uint4 m = *(const uint4*)(g_hm + (size_t)(v0 + vv) * Hn + h0 + q * 8);
            *(uint4*)&hm_sh[vv * 72 + q * 8] = m;
        }
        if (tid < 64) {                 // hp [8b x 64h]: direct fp16 copy
            int b = tid >> 3, q = tid & 7;
            uint4 m = *(const uint4*)(g_hpH + (size_t)(b0 + b) * Hn + h0 + q * 8);
            *(uint4*)&hp_sh[b * 72 + q * 8] = m;
        }
        __syncthreads();

        const __half* hmr0 = &hm_sh[(vbase + g) * 72];
        const __half* hmr1 = &hm_sh[(vbase + g + 8) * 72];

        #pragma unroll
        for (int c = 0; c < 4; c++) {
            const int hb = c * 16;
            unsigned m00 = *(const unsigned*)&hmr0[hb + 2 * t];
            unsigned m10 = *(const unsigned*)&hmr1[hb + 2 * t];
            unsigned m01 = *(const unsigned*)&hmr0[hb + 2 * t + 8];
            unsigned m11 = *(const unsigned*)&hmr1[hb + 2 * t + 8];
            unsigned bw0 = *(const unsigned*)&w2h_sh[h0 + hb + 2 * t];
            unsigned bw1 = *(const unsigned*)&w2h_sh[h0 + hb + 2 * t + 8];
            #pragma unroll
            for (int b = 0; b < 8; b++) {
                unsigned p0 = *(const unsigned*)&hp_sh[b * 72 + hb + 2 * t];
                unsigned p1 = *(const unsigned*)&hp_sh[b * 72 + hb + 2 * t + 8];
                unsigned a0 = tanh2_f16(hadd2u(m00, p0));
                unsigned a1 = tanh2_f16(hadd2u(m10, p0));
                unsigned a2 = tanh2_f16(hadd2u(m01, p1));
                unsigned a3 = tanh2_f16(hadd2u(m11, p1));
                mma_16816(acc[b], a0, a1, a2, a3, bw0, bw1);
            }
        }
    }

    const float b2 = *b2p;
    if (t == 0) {
        #pragma unroll
        for (int b = 0; b < 8; b++) {
            out[(size_t)(b0 + b) * Vn + v0 + vbase + g]     = acc[b][0] + b2;
            out[(size_t)(b0 + b) * Vn + v0 + vbase + g + 8] = acc[b][2] + b2;
        }
    }
}

extern "C" void kernel_launch(void* const* d_in, const int* in_sizes, int n_in,
                              void* d_out, int out_size) {
    const float* patient = (const float*)d_in[0];  // [B, PD]
    const float* atc4    = (const float*)d_in[1];  // [V, MD]
    const float* W1      = (const float*)d_in[2];  // [H, PD+MD]
    const float* b1      = (const float*)d_in[3];  // [H]
    const float* w2      = (const float*)d_in[4];  // [H]
    const float* b2      = (const float*)d_in[5];  // scalar
    float* out = (float*)d_out;                    // [B, V]

    convert_kernel<<<(NP4 + NA4 + NW4) / 256, 256>>>(patient, atc4, W1);
    hmma_gemm_kernel<<<144, 256>>>(b1);

    dim3 grid(Vn / 64, Bn / 8);    // 1024 blocks
    score_kernel<<<grid, 128>>>(w2, b2, out);
}

// round 8
// speedup vs baseline: 1.5834x; 1.0224x over previous
#include <cuda_runtime.h>
#include <cuda_fp16.h>
#include <cstdint>

#define Bn  256
#define Vn  2048
#define PDn 1024
#define MDn 512
#define Hn  512
#define W1LD (PDn + MDn)

// Intermediates (device globals; no allocations).
__device__ __half g_hm[Vn * Hn];          // [v][h]
__device__ __half g_hp2[2 * Bn * Hn];     // two split-K slices, [b][h]; b1 in slice 0

__device__ __forceinline__ unsigned tanh2_f16(unsigned x) {
    unsigned y;
    asm("tanh.approx.f16x2 %0, %1;" : "=r"(y) : "r"(x));
    return y;
}
__device__ __forceinline__ unsigned hadd2u(unsigned a, unsigned b) {
    unsigned d;
    asm("add.rn.f16x2 %0, %1, %2;" : "=r"(d) : "r"(a), "r"(b));
    return d;
}
__device__ __forceinline__ void mma_16816(float c[4],
    unsigned a0, unsigned a1, unsigned a2, unsigned a3,
    unsigned b0, unsigned b1)
{
    asm volatile(
        "mma.sync.aligned.m16n8k16.row.col.f32.f16.f16.f32 "
        "{%0,%1,%2,%3}, {%4,%5,%6,%7}, {%8,%9}, {%0,%1,%2,%3};"
        : "+f"(c[0]), "+f"(c[1]), "+f"(c[2]), "+f"(c[3])
        : "r"(a0), "r"(a1), "r"(a2), "r"(a3), "r"(b0), "r"(b1));
}

// ---------------------------------------------------------------------------
// HMMA GEMM with inline fp32->fp16 conversion. 320 uniform blocks x 256 thr,
// tile 64m x 64h, K=512 per block:
//   bid < 256 : hm   (32 v-tiles x 8 h-tiles), K=512        -> g_hm
//   bid >= 256: hp   (4 b-tiles x 8 h-tiles x splitK2)      -> g_hp2[s]
// Warp tile 32m x 16n (2x2 m16n8k16). smem rows stride 72 halves ->
// conflict-free fragment LDS. Register prefetch of next chunk (fp32).
// ---------------------------------------------------------------------------
__global__ void __launch_bounds__(256) hmma_gemm_kernel(
    const float* __restrict__ patient,
    const float* __restrict__ atc4,
    const float* __restrict__ W1,
    const float* __restrict__ b1)
{
    __shared__ __half As[64 * 72];   // 9.2 KB
    __shared__ __half Ws[64 * 72];   // 9.2 KB

    const int bid = blockIdx.x;
    const int tid = threadIdx.x;

    const float* A;
    __half* dst;
    int LDA, m0, n0, kA0, kW0;
    bool add_b1;

    if (bid < 256) {                  // hm
        A = atc4;  LDA = MDn;  dst = g_hm;
        m0 = (bid & 31) * 64;         // v
        n0 = (bid >> 5) * 64;         // h
        kA0 = 0;  kW0 = PDn;
        add_b1 = false;
    } else {                          // hp split-K2
        int t = bid - 256;            // 0..63
        int s = t & 1;
        A = patient;  LDA = PDn;  dst = g_hp2 + s * (Bn * Hn);
        m0 = ((t >> 1) & 3) * 64;     // b
        n0 = (t >> 3) * 64;           // h
        kA0 = s * 512;  kW0 = s * 512;
        add_b1 = (s == 0);
    }

    const int wid = tid >> 5, lane = tid & 31;
    const int g = lane >> 2, t4 = lane & 3;
    const int wm = wid & 1, wn = wid >> 1;   // 2 x 4 warp grid

    float acc[2][2][4];
    #pragma unroll
    for (int i = 0; i < 2; i++)
        #pragma unroll
        for (int j = 0; j < 2; j++)
            #pragma unroll
            for (int c = 0; c < 4; c++) acc[i][j][c] = 0.0f;

    // Staging: 64 rows x 64 k fp32 per operand per chunk = 1024 float4 each;
    // 4 per thread. r = row, q = float4-column.
    const int sr = tid >> 4;          // base row 0..15 (+16 per it)
    const int sq = tid & 15;          // float4 col 0..15

    float4 fA[4], fW[4];
    auto ldg = [&](int k0) {
        #pragma unroll
        for (int it = 0; it < 4; it++) {
            int r = sr + it * 16;
            fA[it] = *(const float4*)(A  + (size_t)(m0 + r) * LDA  + kA0 + k0 + sq * 4);
            fW[it] = *(const float4*)(W1 + (size_t)(n0 + r) * W1LD + kW0 + k0 + sq * 4);
        }
    };
    auto sts = [&]() {
        #pragma unroll
        for (int it = 0; it < 4; it++) {
            int r = sr + it * 16;
            __half ha[4] = { __float2half_rn(fA[it].x), __float2half_rn(fA[it].y),
                             __float2half_rn(fA[it].z), __float2half_rn(fA[it].w) };
            __half hw[4] = { __float2half_rn(fW[it].x), __float2half_rn(fW[it].y),
                             __float2half_rn(fW[it].z), __float2half_rn(fW[it].w) };
            *(uint2*)&As[r * 72 + sq * 4] = *(uint2*)ha;
            *(uint2*)&Ws[r * 72 + sq * 4] = *(uint2*)hw;
        }
    };

    const int NCH = 512 / 64;         // 8 chunks, uniform for all blocks
    ldg(0);
    sts();
    ldg(64);
    __syncthreads();

    for (int c = 0; c < NCH; c++) {
        #pragma unroll
        for (int ks = 0; ks < 4; ks++) {
            const int kb = ks * 16;
            unsigned a[2][4], b[2][2];
            #pragma unroll
            for (int i = 0; i < 2; i++) {
                int r0 = wm * 32 + i * 16 + g, r1 = r0 + 8;
                a[i][0] = *(const unsigned*)&As[r0 * 72 + kb + 2 * t4];
                a[i][1] = *(const unsigned*)&As[r1 * 72 + kb + 2 * t4];
                a[i][2] = *(const unsigned*)&As[r0 * 72 + kb + 2 * t4 + 8];
                a[i][3] = *(const unsigned*)&As[r1 * 72 + kb + 2 * t4 + 8];
            }
            #pragma unroll
            for (int j = 0; j < 2; j++) {
                int n = wn * 16 + j * 8 + g;
                b[j][0] = *(const unsigned*)&Ws[n * 72 + kb + 2 * t4];
                b[j][1] = *(const unsigned*)&Ws[n * 72 + kb + 2 * t4 + 8];
            }
            #pragma unroll
            for (int i = 0; i < 2; i++)
                #pragma unroll
                for (int j = 0; j < 2; j++)
                    mma_16816(acc[i][j], a[i][0], a[i][1], a[i][2], a[i][3],
                              b[j][0], b[j][1]);
        }
        __syncthreads();
        if (c + 1 < NCH) {
            sts();
            if (c + 2 < NCH) ldg((c + 2) * 64);
            __syncthreads();
        }
    }

    // Epilogue: rows = m (v|b), cols = h; fp16 half2 stores.
    #pragma unroll
    for (int i = 0; i < 2; i++) {
        int r0 = m0 + wm * 32 + i * 16 + g, r1 = r0 + 8;
        #pragma unroll
        for (int j = 0; j < 2; j++) {
            int cn = n0 + wn * 16 + j * 8 + 2 * t4;
            float x0 = acc[i][j][0], x1 = acc[i][j][1];
            float x2 = acc[i][j][2], x3 = acc[i][j][3];
            if (add_b1) {
                float2 bb = *(const float2*)&b1[cn];
                x0 += bb.x; x1 += bb.y; x2 += bb.x; x3 += bb.y;
            }
            *(__half2*)&dst[(size_t)r0 * Hn + cn] = __floats2half2_rn(x0, x1);
            *(__half2*)&dst[(size_t)r1 * Hn + cn] = __floats2half2_rn(x2, x3);
        }
    }
}

// ---------------------------------------------------------------------------
// Score via HMMA: out[b,v] = b2 + sum_h w2[h]*tanh(hp[b,h]+hm[v,h]).
// hp staging sums the two split-K fp16 slices (b1 pre-folded in slice 0).
// Block 128 thr (4 warps), tile 64v x 8b, grid 1024. 8 blocks/SM.
// ---------------------------------------------------------------------------
__global__ void __launch_bounds__(128, 8) score_kernel(
    const float* __restrict__ w2, const float* __restrict__ b2p,
    float* __restrict__ out)
{
    __shared__ __half hm_sh[64 * 72];
    __shared__ __half hp_sh[8 * 72];
    __shared__ __half w2h_sh[Hn];

    const int tid  = threadIdx.x;
    const int v0   = blockIdx.x * 64;
    const int b0   = blockIdx.y * 8;
    const int lane = tid & 31;
    const int g    = lane >> 2;
    const int t    = lane & 3;
    const int vbase = (tid >> 5) * 16;

    {   // w2 -> fp16 once (covered by first __syncthreads)
        float4 w = ((const float4*)w2)[tid];
        __half h4[4] = { __float2half_rn(w.x), __float2half_rn(w.y),
                         __float2half_rn(w.z), __float2half_rn(w.w) };
        *(uint2*)&w2h_sh[tid * 4] = *(uint2*)h4;
    }

    float acc[8][4];
    #pragma unroll
    for (int b = 0; b < 8; b++)
        #pragma unroll
        for (int c = 0; c < 4; c++) acc[b][c] = 0.0f;

    for (int h0 = 0; h0 < Hn; h0 += 64) {
        __syncthreads();
        #pragma unroll
        for (int r = 0; r < 4; r++) {   // hm [64v x 64h]
            int idx = tid + r * 128;
            int vv = idx >> 3, q = idx & 7;
            uint4 m = *(const uint4*)(g_hm + (size_t)(v0 + vv) * Hn + h0 + q * 8);
            *(uint4*)&hm_sh[vv * 72 + q * 8] = m;
        }
        if (tid < 64) {                 // hp [8b x 64h] = slice0 + slice1
            int b = tid >> 3, q = tid & 7;
            size_t off = (size_t)(b0 + b) * Hn + h0 + q * 8;
            uint4 x = *(const uint4*)(g_hp2 + off);
            uint4 y = *(const uint4*)(g_hp2 + Bn * Hn + off);
            uint4 z;
            z.x = hadd2u(x.x, y.x);  z.y = hadd2u(x.y, y.y);
            z.z = hadd2u(x.z, y.z);  z.w = hadd2u(x.w, y.w);
            *(uint4*)&hp_sh[b * 72 + q * 8] = z;
        }
        __syncthreads();

        const __half* hmr0 = &hm_sh[(vbase + g) * 72];
        const __half* hmr1 = &hm_sh[(vbase + g + 8) * 72];

        #pragma unroll
        for (int c = 0; c < 4; c++) {
            const int hb = c * 16;
            unsigned m00 = *(const unsigned*)&hmr0[hb + 2 * t];
            unsigned m10 = *(const unsigned*)&hmr1[hb + 2 * t];
            unsigned m01 = *(const unsigned*)&hmr0[hb + 2 * t + 8];
            unsigned m11 = *(const unsigned*)&hmr1[hb + 2 * t + 8];
            unsigned bw0 = *(const unsigned*)&w2h_sh[h0 + hb + 2 * t];
            unsigned bw1 = *(const unsigned*)&w2h_sh[h0 + hb + 2 * t + 8];
            #pragma unroll
            for (int b = 0; b < 8; b++) {
                unsigned p0 = *(const unsigned*)&hp_sh[b * 72 + hb + 2 * t];
                unsigned p1 = *(const unsigned*)&hp_sh[b * 72 + hb + 2 * t + 8];
                unsigned a0 = tanh2_f16(hadd2u(m00, p0));
                unsigned a1 = tanh2_f16(hadd2u(m10, p0));
                unsigned a2 = tanh2_f16(hadd2u(m01, p1));
                unsigned a3 = tanh2_f16(hadd2u(m11, p1));
                mma_16816(acc[b], a0, a1, a2, a3, bw0, bw1);
            }
        }
    }

    const float b2 = *b2p;
    if (t == 0) {
        #pragma unroll
        for (int b = 0; b < 8; b++) {
            out[(size_t)(b0 + b) * Vn + v0 + vbase + g]     = acc[b][0] + b2;
            out[(size_t)(b0 + b) * Vn + v0 + vbase + g + 8] = acc[b][2] + b2;
        }
    }
}

extern "C" void kernel_launch(void* const* d_in, const int* in_sizes, int n_in,
                              void* d_out, int out_size) {
    const float* patient = (const float*)d_in[0];  // [B, PD]
    const float* atc4    = (const float*)d_in[1];  // [V, MD]
    const float* W1      = (const float*)d_in[2];  // [H, PD+MD]
    const float* b1      = (const float*)d_in[3];  // [H]
    const float* w2      = (const float*)d_in[4];  // [H]
    const float* b2      = (const float*)d_in[5];  // scalar
    float* out = (float*)d_out;                    // [B, V]

    hmma_gemm_kernel<<<320, 256>>>(patient, atc4, W1, b1);

    dim3 grid(Vn / 64, Bn / 8);    // 1024 blocks
    score_kernel<<<grid, 128>>>(w2, b2, out);
}